// round 16
// baseline (speedup 1.0000x reference)
#include <cuda_runtime.h>
#include <math.h>

// Problem constants
#define BB 16
#define CC 48
#define TT 96
#define PATCH 12
#define STEPS 7
#define FF 64
#define ALPHA 0.5f
#define EPS 1e-5f
#define NFEAT (CC*TT)    // 4608
#define CP (CC*PATCH)    // 576
#define SPLIT 3
#define ROWS (CC/SPLIT)  // 16
#define NBLK (BB*PATCH*SPLIT)  // 576
#define NPROD CC               // 48 producer blocks
#define INVR2 0.70710678118654752f

// Scratch (allocation-free rule: __device__ globals)
__device__ float d_xn[BB*NFEAT];
__device__ float d_resbuf[BB*CP];
__device__ float d_tbuf[BB*CP];
__device__ unsigned int d_ctrA[STEPS];
__device__ unsigned int d_ctrB[STEPS];

// ---------------------------------------------------------------------------
// f32x2 packed helpers (sm_103a)
// ---------------------------------------------------------------------------
typedef unsigned long long ull;

__device__ __forceinline__ ull pk2(float lo, float hi) {
    ull r; asm("mov.b64 %0, {%1, %2};" : "=l"(r) : "f"(lo), "f"(hi)); return r;
}
__device__ __forceinline__ void upk2(ull v, float& lo, float& hi) {
    asm("mov.b64 {%0, %1}, %2;" : "=f"(lo), "=f"(hi) : "l"(v));
}
__device__ __forceinline__ ull fma2(ull a, ull b, ull c) {
    ull d; asm("fma.rn.f32x2 %0, %1, %2, %3;" : "=l"(d) : "l"(a), "l"(b), "l"(c)); return d;
}
__device__ __forceinline__ ull mul2(ull a, ull b) {
    ull d; asm("mul.rn.f32x2 %0, %1, %2;" : "=l"(d) : "l"(a), "l"(b)); return d;
}
__device__ __forceinline__ float rcpf(float x) {
    float r; asm("rcp.approx.f32 %0, %1;" : "=f"(r) : "f"(x)); return r;
}

// A&S 7.1.28 scalar: returns erf(|u|) = 1 - (1+a1|u|+..+a6|u|^6)^-16, err<=3e-7
__device__ __forceinline__ float erf_abs(float ax) {
    float h = fmaf(0.0000430638f, ax, 0.0002765672f);
    h = fmaf(h, ax, 0.0001520143f);
    h = fmaf(h, ax, 0.0092705272f);
    h = fmaf(h, ax, 0.0422820123f);
    h = fmaf(h, ax, 0.0705230784f);
    float z = fmaf(h, ax, 1.0f);
    z = z*z; z = z*z; z = z*z; z = z*z;
    return 1.0f - rcpf(z);   // INF -> 0 -> erf=1 (graceful tail)
}
// gelu(a) = 0.5 a (1+erf(a/sqrt2)) = INVR2 * (u + |u|*erf(|u|)), u=a*INVR2
__device__ __forceinline__ float gelu_as(float a) {
    float u  = a * INVR2;
    float ax = fabsf(u);
    return INVR2 * fmaf(ax, erf_abs(ax), u);
}

// Packed edge GELU*1: returns g = u*(1+erf(u)) = u + |u|*(1 - z^-16)
__device__ __forceinline__ ull edge_gelu2(ull wx, ull zi, ull vv) {
    const ull ABSM = 0x7FFFFFFF7FFFFFFFULL;
    const ull CA6 = pk2(0.0000430638f, 0.0000430638f);
    const ull CA5 = pk2(0.0002765672f, 0.0002765672f);
    const ull CA4 = pk2(0.0001520143f, 0.0001520143f);
    const ull CA3 = pk2(0.0092705272f, 0.0092705272f);
    const ull CA2 = pk2(0.0422820123f, 0.0422820123f);
    const ull CA1 = pk2(0.0705230784f, 0.0705230784f);
    const ull ONE2 = pk2(1.0f, 1.0f);
    const ull NEG2 = pk2(-1.0f, -1.0f);

    ull u  = fma2(wx, zi, vv);
    ull ax = u & ABSM;
    ull h  = fma2(CA6, ax, CA5);
    h = fma2(h, ax, CA4);
    h = fma2(h, ax, CA3);
    h = fma2(h, ax, CA2);
    h = fma2(h, ax, CA1);
    ull z = fma2(h, ax, ONE2);
    z = mul2(z, z);
    z = mul2(z, z);
    z = mul2(z, z);
    z = mul2(z, z);                    // z^16
    float f0, f1; upk2(z, f0, f1);
    ull r = pk2(rcpf(f0), rcpf(f1));   // z^-16
    ull omr = fma2(r, NEG2, ONE2);     // 1 - r   (no sign LOPs)
    return fma2(ax, omr, u);           // u + |u|*(1-r)
}

// ---------------------------------------------------------------------------
// Kernel 0: BatchNorm over batch for all C*T features; writes xn and first
// patch directly into d_out. Also resets all step barrier counters.
// ---------------------------------------------------------------------------
__global__ void bn0_kernel(const float* __restrict__ x,
                           const float* __restrict__ g0,
                           const float* __restrict__ b0,
                           float* __restrict__ out)
{
    int f = blockIdx.x * blockDim.x + threadIdx.x;
    if (f < STEPS) { d_ctrA[f] = 0u; d_ctrB[f] = 0u; }
    if (f >= NFEAT) return;
    float v[BB];
    float sum = 0.f;
    #pragma unroll
    for (int b = 0; b < BB; b++) { v[b] = x[b*NFEAT + f]; sum += v[b]; }
    float mu = sum * (1.0f/BB);
    float var = 0.f;
    #pragma unroll
    for (int b = 0; b < BB; b++) { float d = v[b] - mu; var = fmaf(d, d, var); }
    var *= (1.0f/BB);
    float rs = rsqrtf(var + EPS);
    float g = g0[f], bb0 = b0[f];
    int t = f % TT;
    #pragma unroll
    for (int b = 0; b < BB; b++) {
        float y = (v[b] - mu) * rs * g + bb0;
        d_xn[b*NFEAT + f] = y;
        if (t < PATCH) out[b*NFEAT + f] = y;
    }
}

// ---------------------------------------------------------------------------
// Barrier helpers
// ---------------------------------------------------------------------------
__device__ __forceinline__ void arrive(unsigned int* ctr) {
    asm volatile("red.release.gpu.global.add.u32 [%0], %1;"
                 :: "l"(ctr), "r"(1u) : "memory");
}
__device__ __forceinline__ void spin_until(unsigned int* ctr, unsigned int n) {
    unsigned int v;
    do {
        asm volatile("ld.acquire.gpu.global.u32 %0, [%1];"
                     : "=r"(v) : "l"(ctr) : "memory");
        if (v < n) __nanosleep(32);
    } while (v < n);
}

// ---------------------------------------------------------------------------
// Persistent fused kernel: 576 blocks x 192 threads, all 7 steps internal.
// All 576 blocks are co-resident (launch_bounds(192,4): 4 blk/SM x 148 = 592),
// so the flag barriers cannot deadlock.
//   Producers (blocks 0..47): wait ctrB[s-1]==576 -> A-phase (BN1/Wagg/gelu/
//     +xw/BN2 -> tbuf,resbuf) -> release ctrA[s].
//   All blocks: wait ctrA[s]==48 -> B-phase (edge MLP packed A&S gelu, top-3,
//     softmax, aggregate) -> write out column 12s+12+p -> arrive ctrB[s].
// ---------------------------------------------------------------------------
__global__ __launch_bounds__(192, 4) void fused_kernel(
    float* __restrict__ out,
    const float* __restrict__ g1, const float* __restrict__ b1,
    const float* __restrict__ g2, const float* __restrict__ b2,
    const float* __restrict__ Wagg, const float* __restrict__ bagg,
    const float* __restrict__ W1, const float* __restrict__ bm1,
    const float* __restrict__ W2, const float* __restrict__ bm2,
    const float* __restrict__ wmsg, const float* __restrict__ bmsg)
{
    int blk = blockIdx.x;            // 0..575
    int tid = threadIdx.x;           // 0..191

    __shared__ float  sT[CC], sMsg[CC], sRes[CC];
    __shared__ ulonglong2 sWA[FF];   // {(wx,wx),(w2,w2)}
    __shared__ ulonglong2 sWB[FF];   // {(wy,wy),(bb,bb)}
    __shared__ float  sE[ROWS*CC];   // 768
    __shared__ float  sBn[PATCH*16]; // A-phase scratch

    // Pack MLP weights ONCE.
    if (tid >= 64 && tid < 128) {
        int f = tid - 64;
        float wx = W1[2*f]   * INVR2;
        float wy = W1[2*f+1] * INVR2;
        float wb = bm1[f]    * INVR2;
        float w2 = W2[f]     * INVR2;
        ulonglong2 wa;  wa.x  = pk2(wx, wx); wa.y  = pk2(w2, w2);
        ulonglong2 wbv; wbv.x = pk2(wy, wy); wbv.y = pk2(wb, wb);
        sWA[f] = wa;
        sWB[f] = wbv;
    }

    int bp  = blk / SPLIT;
    int seg = blk % SPLIT;
    int b = bp / PATCH;
    int p = bp % PATCH;
    int jj = tid % CC;
    int rbase = tid / CC;            // 0..3
    float bm2v = bm2[0];

    for (int s = 0; s < STEPS; s++) {
        // ------------- A-phase (producer blocks only) -------------
        if (blk < NPROD) {
            if (s > 0) {
                if (tid == 0) spin_until(&d_ctrB[s-1], NBLK);
                __syncthreads();
                __threadfence();
            }
            int c = blk;
            int pa = tid >> 4;       // 0..11
            int ba = tid & 15;       // 0..15

            float v = out[ba*NFEAT + c*TT + 12*s + pa];

            float sum = v;
            #pragma unroll
            for (int m = 1; m < 16; m <<= 1) sum += __shfl_xor_sync(0xffffffffu, sum, m);
            float mu = sum * (1.0f/16.0f);
            float d = v - mu;
            float q = d * d;
            #pragma unroll
            for (int m = 1; m < 16; m <<= 1) q += __shfl_xor_sync(0xffffffffu, q, m);
            float rs = rsqrtf(q * (1.0f/16.0f) + EPS);
            float bn = d * rs * g1[c*PATCH + pa] + b1[c*PATCH + pa];
            sBn[pa*16 + ba] = bn;
            __syncthreads();

            float acc = bagg[pa];
            #pragma unroll
            for (int pp = 0; pp < PATCH; pp++)
                acc = fmaf(sBn[pp*16 + ba], Wagg[pa*PATCH + pp], acc);
            float inp = gelu_as(acc);
            float res = inp + d_xn[ba*NFEAT + c*TT + 12*s + PATCH + pa];

            float sum2 = res;
            #pragma unroll
            for (int m = 1; m < 16; m <<= 1) sum2 += __shfl_xor_sync(0xffffffffu, sum2, m);
            float mu2 = sum2 * (1.0f/16.0f);
            float d2 = res - mu2;
            float q2 = d2 * d2;
            #pragma unroll
            for (int m = 1; m < 16; m <<= 1) q2 += __shfl_xor_sync(0xffffffffu, q2, m);
            float rs2 = rsqrtf(q2 * (1.0f/16.0f) + EPS);
            float tv = d2 * rs2 * g2[c*PATCH + pa] + b2[c*PATCH + pa];

            d_tbuf[ba*CP + c*PATCH + pa] = tv;
            d_resbuf[ba*CP + c*PATCH + pa] = res;

            __threadfence();
            __syncthreads();
            if (tid == 0) arrive(&d_ctrA[s]);
        }

        // ------------- barrier: wait for 48 producers -------------
        if (tid == 0) spin_until(&d_ctrA[s], NPROD);
        __syncthreads();
        __threadfence();

        // ------------- B-phase -------------
        if (tid < CC) {
            float tv = d_tbuf[b*CP + tid*PATCH + p];
            sT[tid]   = tv;
            sMsg[tid] = fmaf(tv, wmsg[0], bmsg[0]);
            sRes[tid] = d_resbuf[b*CP + tid*PATCH + p];
        }
        __syncthreads();

        float zjv = sT[jj];
        ull zjpk = pk2(zjv, zjv);

        ull zi01 = pk2(sT[seg*ROWS + rbase],     sT[seg*ROWS + rbase + 4]);
        ull zi23 = pk2(sT[seg*ROWS + rbase + 8], sT[seg*ROWS + rbase + 12]);
        ull acc01 = pk2(bm2v, bm2v);
        ull acc23 = acc01;

        #pragma unroll 8
        for (int f = 0; f < FF; f++) {
            ulonglong2 wa = sWA[f];
            ulonglong2 wb = sWB[f];
            ull vv = fma2(wb.x, zjpk, wb.y);
            acc01 = fma2(wa.y, edge_gelu2(wa.x, zi01, vv), acc01);
            acc23 = fma2(wa.y, edge_gelu2(wa.x, zi23, vv), acc23);
        }

        {
            float e0, e1, e2, e3;
            upk2(acc01, e0, e1);
            upk2(acc23, e2, e3);
            sE[(rbase     )*CC + jj] = e0;
            sE[(rbase +  4)*CC + jj] = e1;
            sE[(rbase +  8)*CC + jj] = e2;
            sE[(rbase + 12)*CC + jj] = e3;
        }
        __syncthreads();

        // top-3 + softmax + aggregate: one thread per row
        if (tid < ROWS) {
            int i = seg*ROWS + tid;
            const float* row = &sE[tid*CC];
            float v0 = -1e30f, v1 = -1e30f, v2 = -1e30f;
            int   i0 = 0,      i1 = 0,      i2 = 0;
            #pragma unroll 4
            for (int j = 0; j < CC; j++) {
                float e = row[j];
                if (e > v0)      { v2=v1; i2=i1; v1=v0; i1=i0; v0=e; i0=j; }
                else if (e > v1) { v2=v1; i2=i1; v1=e;  i1=j; }
                else if (e > v2) { v2=e;  i2=j; }
            }
            float e1 = expf(v1 - v0), e2 = expf(v2 - v0);
            float inv = 1.0f / (1.0f + e1 + e2);
            float zn = (sMsg[i0] + e1*sMsg[i1] + e2*sMsg[i2]) * inv;
            float o = sRes[i] + ALPHA * zn;
            out[b*NFEAT + i*TT + 12*s + PATCH + p] = o;   // prev for step s+1
        }

        __threadfence();
        __syncthreads();
        if (tid == 0) arrive(&d_ctrB[s]);
    }
}

// ---------------------------------------------------------------------------
extern "C" void kernel_launch(void* const* d_in, const int* in_sizes, int n_in,
                              void* d_out, int out_size)
{
    const float* x    = (const float*)d_in[0];
    const float* g0   = (const float*)d_in[1];
    const float* b0   = (const float*)d_in[2];
    const float* g1   = (const float*)d_in[3];
    const float* b1   = (const float*)d_in[4];
    const float* g2   = (const float*)d_in[5];
    const float* b2   = (const float*)d_in[6];
    const float* Wagg = (const float*)d_in[7];
    const float* bagg = (const float*)d_in[8];
    const float* W1   = (const float*)d_in[9];
    const float* bm1  = (const float*)d_in[10];
    const float* W2   = (const float*)d_in[11];
    const float* bm2  = (const float*)d_in[12];
    const float* wmsg = (const float*)d_in[13];
    const float* bmsg = (const float*)d_in[14];
    float* out = (float*)d_out;

    bn0_kernel<<<(NFEAT + 255)/256, 256>>>(x, g0, b0, out);

    fused_kernel<<<NBLK, 192>>>(out, g1, b1, g2, b2, Wagg, bagg,
                                W1, bm1, W2, bm2, wmsg, bmsg);
}

// round 17
// speedup vs baseline: 1.0374x; 1.0374x over previous
#include <cuda_runtime.h>
#include <math.h>

// Problem constants
#define BB 16
#define CC 48
#define TT 96
#define PATCH 12
#define STEPS 7
#define FF 64
#define ALPHA 0.5f
#define EPS 1e-5f
#define NFEAT (CC*TT)    // 4608
#define CP (CC*PATCH)    // 576
#define SPLIT 3
#define ROWS (CC/SPLIT)  // 16
#define NBLK (BB*PATCH*SPLIT)  // 576
#define INVR2 0.70710678118654752f

// Scratch (allocation-free rule: __device__ globals)
__device__ float d_xn[BB*NFEAT];
__device__ float d_state[2][BB*CP];    // ping-pong scan state, layout [b][c*12+p]
__device__ unsigned int d_ctr[STEPS];

// ---------------------------------------------------------------------------
// f32x2 packed helpers (sm_103a)
// ---------------------------------------------------------------------------
typedef unsigned long long ull;

__device__ __forceinline__ ull pk2(float lo, float hi) {
    ull r; asm("mov.b64 %0, {%1, %2};" : "=l"(r) : "f"(lo), "f"(hi)); return r;
}
__device__ __forceinline__ void upk2(ull v, float& lo, float& hi) {
    asm("mov.b64 {%0, %1}, %2;" : "=f"(lo), "=f"(hi) : "l"(v));
}
__device__ __forceinline__ ull fma2(ull a, ull b, ull c) {
    ull d; asm("fma.rn.f32x2 %0, %1, %2, %3;" : "=l"(d) : "l"(a), "l"(b), "l"(c)); return d;
}
__device__ __forceinline__ ull mul2(ull a, ull b) {
    ull d; asm("mul.rn.f32x2 %0, %1, %2;" : "=l"(d) : "l"(a), "l"(b)); return d;
}
__device__ __forceinline__ float rcpf(float x) {
    float r; asm("rcp.approx.f32 %0, %1;" : "=f"(r) : "f"(x)); return r;
}

// A&S 7.1.28 scalar: erf(|u|) = 1 - (1+a1|u|+..+a6|u|^6)^-16, err<=3e-7
__device__ __forceinline__ float gelu_as(float a) {
    float u  = a * INVR2;
    float ax = fabsf(u);
    float h = fmaf(0.0000430638f, ax, 0.0002765672f);
    h = fmaf(h, ax, 0.0001520143f);
    h = fmaf(h, ax, 0.0092705272f);
    h = fmaf(h, ax, 0.0422820123f);
    h = fmaf(h, ax, 0.0705230784f);
    float z = fmaf(h, ax, 1.0f);
    z = z*z; z = z*z; z = z*z; z = z*z;
    float er = 1.0f - rcpf(z);
    return INVR2 * fmaf(ax, er, u);
}

// Packed edge GELU: returns g = u*(1+erf(u)) = u + |u|*(1 - z^-16)
__device__ __forceinline__ ull edge_gelu2(ull wx, ull zi, ull vv) {
    const ull ABSM = 0x7FFFFFFF7FFFFFFFULL;
    const ull CA6 = pk2(0.0000430638f, 0.0000430638f);
    const ull CA5 = pk2(0.0002765672f, 0.0002765672f);
    const ull CA4 = pk2(0.0001520143f, 0.0001520143f);
    const ull CA3 = pk2(0.0092705272f, 0.0092705272f);
    const ull CA2 = pk2(0.0422820123f, 0.0422820123f);
    const ull CA1 = pk2(0.0705230784f, 0.0705230784f);
    const ull ONE2 = pk2(1.0f, 1.0f);
    const ull NEG2 = pk2(-1.0f, -1.0f);

    ull u  = fma2(wx, zi, vv);
    ull ax = u & ABSM;
    ull h  = fma2(CA6, ax, CA5);
    h = fma2(h, ax, CA4);
    h = fma2(h, ax, CA3);
    h = fma2(h, ax, CA2);
    h = fma2(h, ax, CA1);
    ull z = fma2(h, ax, ONE2);
    z = mul2(z, z);
    z = mul2(z, z);
    z = mul2(z, z);
    z = mul2(z, z);                    // z^16
    float f0, f1; upk2(z, f0, f1);
    ull r = pk2(rcpf(f0), rcpf(f1));   // z^-16
    ull omr = fma2(r, NEG2, ONE2);     // 1 - r
    return fma2(ax, omr, u);           // u + |u|*(1-r)
}

// ---------------------------------------------------------------------------
// Kernel 0: BN over batch for all C*T features; writes xn, the first patch
// into d_out AND d_state[0]; resets barrier counters.
// ---------------------------------------------------------------------------
__global__ void bn0_kernel(const float* __restrict__ x,
                           const float* __restrict__ g0,
                           const float* __restrict__ b0,
                           float* __restrict__ out)
{
    int f = blockIdx.x * blockDim.x + threadIdx.x;
    if (f < STEPS) d_ctr[f] = 0u;
    if (f >= NFEAT) return;
    float v[BB];
    float sum = 0.f;
    #pragma unroll
    for (int b = 0; b < BB; b++) { v[b] = x[b*NFEAT + f]; sum += v[b]; }
    float mu = sum * (1.0f/BB);
    float var = 0.f;
    #pragma unroll
    for (int b = 0; b < BB; b++) { float d = v[b] - mu; var = fmaf(d, d, var); }
    var *= (1.0f/BB);
    float rs = rsqrtf(var + EPS);
    float g = g0[f], bb0 = b0[f];
    int c = f / TT, t = f % TT;
    #pragma unroll
    for (int b = 0; b < BB; b++) {
        float y = (v[b] - mu) * rs * g + bb0;
        d_xn[b*NFEAT + f] = y;
        if (t < PATCH) {
            out[b*NFEAT + f] = y;
            d_state[0][b*CP + c*PATCH + t] = y;
        }
    }
}

// ---------------------------------------------------------------------------
// Barrier helpers (release/acquire on the counter; no extra fences needed)
// ---------------------------------------------------------------------------
__device__ __forceinline__ void arrive(unsigned int* ctr) {
    asm volatile("red.release.gpu.global.add.u32 [%0], %1;"
                 :: "l"(ctr), "r"(1u) : "memory");
}
__device__ __forceinline__ void spin_until(unsigned int* ctr, unsigned int n) {
    unsigned int v;
    do {
        asm volatile("ld.acquire.gpu.global.u32 %0, [%1];"
                     : "=r"(v) : "l"(ctr) : "memory");
        if (v < n) __nanosleep(32);
    } while (v < n);
}

// ---------------------------------------------------------------------------
// Persistent fused kernel: 576 blocks x 192 threads, 7 steps, ONE global
// barrier per step. Every block redundantly computes the (cheap, coalesced)
// A-phase from the compact ping-pong state buffer, then its B-phase slab.
// ---------------------------------------------------------------------------
__global__ __launch_bounds__(192, 4) void fused_kernel(
    float* __restrict__ out,
    const float* __restrict__ g1, const float* __restrict__ b1,
    const float* __restrict__ g2, const float* __restrict__ b2,
    const float* __restrict__ Wagg, const float* __restrict__ bagg,
    const float* __restrict__ W1, const float* __restrict__ bm1,
    const float* __restrict__ W2, const float* __restrict__ bm2,
    const float* __restrict__ wmsg, const float* __restrict__ bmsg)
{
    int blk = blockIdx.x;            // 0..575
    int tid = threadIdx.x;           // 0..191

    __shared__ float  sT[CC], sMsg[CC], sResRow[CC];
    __shared__ ulonglong2 sWA[FF];   // {(wx,wx),(w2,w2)}
    __shared__ ulonglong2 sWB[FF];   // {(wy,wy),(bb,bb)}
    __shared__ float  sE[ROWS*CC];   // 768
    __shared__ float  sA[CP];        // rs*g1*wg[pp] per feature
    __shared__ float  sBt[CP];       // b1 - mu*rs*g1 per feature
    __shared__ float  sBW[CC];       // per-channel const of matmul
    __shared__ float  sRes16[BB*CC]; // res[b'][c] at this block's p
    __shared__ float  sWg[PATCH];    // Wagg row p
    __shared__ float  sTopV[ROWS][4][3];
    __shared__ int    sTopI[ROWS][4][3];

    int bp  = blk / SPLIT;
    int seg = blk % SPLIT;
    int b = bp / PATCH;
    int p = bp % PATCH;
    int jj = tid % CC;
    int rbase = tid / CC;            // 0..3
    float bm2v = bm2[0];
    float wm = wmsg[0], bm = bmsg[0];

    // Pack MLP weights + Wagg row ONCE.
    if (tid >= 64 && tid < 128) {
        int f = tid - 64;
        float wx = W1[2*f]   * INVR2;
        float wy = W1[2*f+1] * INVR2;
        float wb = bm1[f]    * INVR2;
        float w2 = W2[f]     * INVR2;
        ulonglong2 wa;  wa.x  = pk2(wx, wx); wa.y  = pk2(w2, w2);
        ulonglong2 wbv; wbv.x = pk2(wy, wy); wbv.y = pk2(wb, wb);
        sWA[f] = wa;
        sWB[f] = wbv;
    }
    if (tid < PATCH) sWg[tid] = Wagg[p*PATCH + tid];
    __syncthreads();

    for (int s = 0; s < STEPS; s++) {
        const float* Pin = d_state[s & 1];
        float*       Pout = d_state[(s + 1) & 1];

        if (s > 0) {
            if (tid == 0) spin_until(&d_ctr[s-1], NBLK);
            __syncthreads();
        }

        // ---- Phase 1a: BN1 stats for all 576 features, folded affine ----
        {
            int pp = tid % PATCH;            // 192 % 12 == 0 -> constant
            float wgpp = sWg[pp];
            #pragma unroll
            for (int k = 0; k < 3; k++) {
                int f = tid + k*192;
                float v[BB];
                float sum = 0.f;
                #pragma unroll
                for (int x = 0; x < BB; x++) { v[x] = Pin[x*CP + f]; sum += v[x]; }
                float mu = sum * (1.0f/BB);
                float var = 0.f;
                #pragma unroll
                for (int x = 0; x < BB; x++) { float d = v[x] - mu; var = fmaf(d, d, var); }
                float rs = rsqrtf(var * (1.0f/BB) + EPS);
                float a = rs * g1[f];
                sA[f]  = a * wgpp;
                sBt[f] = b1[f] - mu * a;
            }
        }
        __syncthreads();

        // ---- Phase 1b: per-channel constant term ----
        if (tid < CC) {
            float acc = bagg[p];
            #pragma unroll
            for (int pp = 0; pp < PATCH; pp++)
                acc = fmaf(sBt[tid*PATCH + pp], sWg[pp], acc);
            sBW[tid] = acc;
        }
        __syncthreads();

        // ---- Phase 1c: matmul row p + GELU + residual, all (b',c) ----
        {
            int c = tid % CC;                // fixed per thread
            float aw[PATCH];
            #pragma unroll
            for (int pp = 0; pp < PATCH; pp++) aw[pp] = sA[c*PATCH + pp];
            float bw = sBW[c];
            #pragma unroll
            for (int u = 0; u < 4; u++) {
                int bx = tid / CC + 4*u;
                const float4* pr = (const float4*)(Pin + bx*CP + c*PATCH);
                float4 q0 = pr[0], q1 = pr[1], q2 = pr[2];
                float acc = bw;
                acc = fmaf(q0.x, aw[0], acc);  acc = fmaf(q0.y, aw[1], acc);
                acc = fmaf(q0.z, aw[2], acc);  acc = fmaf(q0.w, aw[3], acc);
                acc = fmaf(q1.x, aw[4], acc);  acc = fmaf(q1.y, aw[5], acc);
                acc = fmaf(q1.z, aw[6], acc);  acc = fmaf(q1.w, aw[7], acc);
                acc = fmaf(q2.x, aw[8], acc);  acc = fmaf(q2.y, aw[9], acc);
                acc = fmaf(q2.z, aw[10], acc); acc = fmaf(q2.w, aw[11], acc);
                float res = gelu_as(acc) + d_xn[bx*NFEAT + c*TT + 12*s + PATCH + p];
                sRes16[bx*CC + c] = res;
            }
        }
        __syncthreads();

        // ---- Phase 1d: BN2 over batch (192 threads, 4-lane shuffle) ----
        {
            int c = tid >> 2;                // 0..47
            int q = tid & 3;
            float part = 0.f;
            #pragma unroll
            for (int x = 0; x < 4; x++) part += sRes16[(q*4 + x)*CC + c];
            part += __shfl_xor_sync(0xffffffffu, part, 1);
            part += __shfl_xor_sync(0xffffffffu, part, 2);
            float mu = part * (1.0f/BB);
            float var = 0.f;
            #pragma unroll
            for (int x = 0; x < 4; x++) {
                float d = sRes16[(q*4 + x)*CC + c] - mu;
                var = fmaf(d, d, var);
            }
            var += __shfl_xor_sync(0xffffffffu, var, 1);
            var += __shfl_xor_sync(0xffffffffu, var, 2);
            if (q == 0) {
                float rs = rsqrtf(var * (1.0f/BB) + EPS);
                float rme = sRes16[b*CC + c];
                float tv = (rme - mu) * rs * g2[c*PATCH + p] + b2[c*PATCH + p];
                sT[c] = tv;
                sMsg[c] = fmaf(tv, wm, bm);
                sResRow[c] = rme;
            }
        }
        __syncthreads();

        // ---- Phase 2: edge MLP slab (packed A&S GELU) ----
        {
            float zjv = sT[jj];
            ull zjpk = pk2(zjv, zjv);
            ull zi01 = pk2(sT[seg*ROWS + rbase],     sT[seg*ROWS + rbase + 4]);
            ull zi23 = pk2(sT[seg*ROWS + rbase + 8], sT[seg*ROWS + rbase + 12]);
            ull acc01 = pk2(bm2v, bm2v);
            ull acc23 = acc01;

            #pragma unroll 8
            for (int f = 0; f < FF; f++) {
                ulonglong2 wa = sWA[f];
                ulonglong2 wb = sWB[f];
                ull vv = fma2(wb.x, zjpk, wb.y);
                acc01 = fma2(wa.y, edge_gelu2(wa.x, zi01, vv), acc01);
                acc23 = fma2(wa.y, edge_gelu2(wa.x, zi23, vv), acc23);
            }
            float e0, e1, e2, e3;
            upk2(acc01, e0, e1);
            upk2(acc23, e2, e3);
            sE[(rbase     )*CC + jj] = e0;
            sE[(rbase +  4)*CC + jj] = e1;
            sE[(rbase +  8)*CC + jj] = e2;
            sE[(rbase + 12)*CC + jj] = e3;
        }
        __syncthreads();

        // ---- top-3 scan: 64 threads, 12 j's each (ascending j, strict >) ----
        if (tid < 64) {
            int row = tid >> 2;
            int lane = tid & 3;
            const float* r = &sE[row*CC + lane*12];
            float v0 = -1e30f, v1 = -1e30f, v2 = -1e30f;
            int   i0 = 0,      i1 = 0,      i2 = 0;
            #pragma unroll
            for (int j = 0; j < 12; j++) {
                float e = r[j];
                int jg = lane*12 + j;
                if (e > v0)      { v2=v1; i2=i1; v1=v0; i1=i0; v0=e; i0=jg; }
                else if (e > v1) { v2=v1; i2=i1; v1=e;  i1=jg; }
                else if (e > v2) { v2=e;  i2=jg; }
            }
            sTopV[row][lane][0] = v0; sTopI[row][lane][0] = i0;
            sTopV[row][lane][1] = v1; sTopI[row][lane][1] = i1;
            sTopV[row][lane][2] = v2; sTopI[row][lane][2] = i2;
        }
        __syncthreads();

        // ---- merge 12 candidates + softmax + aggregate + write ----
        if (tid < ROWS) {
            float v0 = -1e30f, v1 = -1e30f, v2 = -1e30f;
            int   i0 = 0,      i1 = 0,      i2 = 0;
            #pragma unroll
            for (int l = 0; l < 4; l++) {
                #pragma unroll
                for (int k = 0; k < 3; k++) {
                    float e = sTopV[tid][l][k];
                    int jg = sTopI[tid][l][k];
                    if (e > v0)      { v2=v1; i2=i1; v1=v0; i1=i0; v0=e; i0=jg; }
                    else if (e > v1) { v2=v1; i2=i1; v1=e;  i1=jg; }
                    else if (e > v2) { v2=e;  i2=jg; }
                }
            }
            float e1 = expf(v1 - v0), e2 = expf(v2 - v0);
            float inv = 1.0f / (1.0f + e1 + e2);
            float zn = (sMsg[i0] + e1*sMsg[i1] + e2*sMsg[i2]) * inv;
            int i = seg*ROWS + tid;
            float o = sResRow[i] + ALPHA * zn;
            out[b*NFEAT + i*TT + 12*s + PATCH + p] = o;
            Pout[b*CP + i*PATCH + p] = o;          // next step's prev
        }

        __syncthreads();
        if (s < STEPS-1 && tid == 0) arrive(&d_ctr[s]);
    }
}

// ---------------------------------------------------------------------------
extern "C" void kernel_launch(void* const* d_in, const int* in_sizes, int n_in,
                              void* d_out, int out_size)
{
    const float* x    = (const float*)d_in[0];
    const float* g0   = (const float*)d_in[1];
    const float* b0   = (const float*)d_in[2];
    const float* g1   = (const float*)d_in[3];
    const float* b1   = (const float*)d_in[4];
    const float* g2   = (const float*)d_in[5];
    const float* b2   = (const float*)d_in[6];
    const float* Wagg = (const float*)d_in[7];
    const float* bagg = (const float*)d_in[8];
    const float* W1   = (const float*)d_in[9];
    const float* bm1  = (const float*)d_in[10];
    const float* W2   = (const float*)d_in[11];
    const float* bm2  = (const float*)d_in[12];
    const float* wmsg = (const float*)d_in[13];
    const float* bmsg = (const float*)d_in[14];
    float* out = (float*)d_out;

    bn0_kernel<<<(NFEAT + 255)/256, 256>>>(x, g0, b0, out);

    fused_kernel<<<NBLK, 192>>>(out, g1, b1, g2, b2, Wagg, bagg,
                                W1, bm1, W2, bm2, wmsg, bmsg);
}